// round 15
// baseline (speedup 1.0000x reference)
#include <cuda_runtime.h>
#include <cuda_bf16.h>
#include <cuda_fp16.h>
#include <math.h>
#include <stdint.h>

#define T_SEQ 2048
#define D_MOD 256
#define N_BH  32
#define M_TOT (N_BH * T_SEQ)   /* 65536 */
#define EPS_F 1e-8f
#define KCAT  1024              /* split-fp16 K for o-projection */
#define KSC   512               /* fp16 K for scores / gate / qkv projections */

// ---- scratch (device globals; no runtime allocation allowed) ----
__device__ float g_outr[M_TOT * D_MOD];
__device__ float g_outi[M_TOT * D_MOD];
__device__ float g_sc[(size_t)N_BH * T_SEQ * T_SEQ];          /* 512 MB fp32 scores */
__device__ __half g_attn[(size_t)N_BH * T_SEQ * T_SEQ];       /* 256 MB fp16 attn  */
__device__ __half g_qcat[(size_t)M_TOT * KSC];                /* 64 MB  [hr|hi] / magcat */
__device__ __half g_kcat[(size_t)M_TOT * KSC];                /* 64 MB  [hr|hi]    */
__device__ __half g_vcat[(size_t)M_TOT * KSC];                /* 64 MB  [hr|hi]    */
__device__ __half g_acat1[(size_t)M_TOT * KSC];               /* 64 MB  q input acat */
__device__ __half g_acat2[(size_t)M_TOT * KSC];               /* 64 MB  kv input acat */
__device__ __half g_acat3[(size_t)M_TOT * KCAT];              /* 128 MB ctx h/l acat */
__device__ __half g_vtr[(size_t)N_BH * D_MOD * T_SEQ];        /* 32 MB V^T fp16    */
__device__ __half g_vti[(size_t)N_BH * D_MOD * T_SEQ];        /* 32 MB V^T fp16    */
__device__ __half g_wq[512 * KSC];                            /* 0.5 MB weight cat */
__device__ __half g_wk[512 * KSC];
__device__ __half g_wv[512 * KSC];
__device__ __half g_wo[512 * KCAT];                           /* 1 MB (o keeps K=1024) */
__device__ __half g_wg[256 * KSC];                            /* gate W cat        */

// ============================================================================
// helpers
// ============================================================================
__device__ __forceinline__ uint32_t smem_to_u32(const void* smem_ptr) {
    uint32_t addr;
    asm("{ .reg .u64 tmp; cvta.to.shared.u64 tmp, %1; cvt.u32.u64 %0, tmp; }"
        : "=r"(addr) : "l"(smem_ptr));
    return addr;
}
__device__ __forceinline__ void cp16(uint32_t smem_addr, const void* gptr) {
    asm volatile("cp.async.cg.shared.global [%0], [%1], 16;"
                 :: "r"(smem_addr), "l"(gptr) : "memory");
}
__device__ __forceinline__ void ldsm_x4(uint32_t* r, uint32_t addr) {
    asm volatile("ldmatrix.sync.aligned.m8n8.x4.shared.b16 {%0,%1,%2,%3}, [%4];"
                 : "=r"(r[0]), "=r"(r[1]), "=r"(r[2]), "=r"(r[3]) : "r"(addr));
}
__device__ __forceinline__ void ldsm_x2(uint32_t* r, uint32_t addr) {
    asm volatile("ldmatrix.sync.aligned.m8n8.x2.shared.b16 {%0,%1}, [%2];"
                 : "=r"(r[0]), "=r"(r[1]) : "r"(addr));
}
__device__ __forceinline__ void mma_f16(float* d, const uint32_t* a, const uint32_t* b) {
    asm volatile(
        "mma.sync.aligned.m16n8k16.row.col.f32.f16.f16.f32 "
        "{%0,%1,%2,%3}, {%4,%5,%6,%7}, {%8,%9}, {%0,%1,%2,%3};"
        : "+f"(d[0]), "+f"(d[1]), "+f"(d[2]), "+f"(d[3])
        : "r"(a[0]), "r"(a[1]), "r"(a[2]), "r"(a[3]), "r"(b[0]), "r"(b[1]));
}
__device__ __forceinline__ uint32_t pack_h2(float a, float b) {
    __half2 t = __floats2half2_rn(a, b);
    return *(uint32_t*)&t;
}

// ============================================================================
// Core 128x128 NT tile GEMM on mma.sync fp16 (A,B K-major), fp32 accum.
// 256 threads = 8 warps in 2(m) x 4(n); warp tile 64x32; Kblk=32.
// 3-stage cp.async pipeline in dynamic smem (61440 B).
// Epilogue callback: epi(row, col, v0, v1).
// ============================================================================
#define SBUF_B   10240u
#define STAGE_B  20480u

template<int KTOT, typename Epi>
__device__ __forceinline__ void gemm_mma_core(
    const uint16_t* __restrict__ Ag, const uint16_t* __restrict__ Bg, Epi epi)
{
    extern __shared__ uint16_t sh16[];
    const uint32_t base = smem_to_u32(sh16);
    const int tid = threadIdx.x;
    const int wid = tid >> 5, lane = tid & 31;
    const int wm = wid & 1, wn = wid >> 1;

    float acc[4][4][4];
#pragma unroll
    for (int i = 0; i < 4; i++)
#pragma unroll
        for (int j = 0; j < 4; j++)
#pragma unroll
            for (int v = 0; v < 4; v++) acc[i][j][v] = 0.f;

    const int c0 = tid, c1 = tid + 256;
    const int r0 = c0 >> 2, o0 = (c0 & 3) * 8;
    const int r1 = c1 >> 2, o1 = (c1 & 3) * 8;
    const uint32_t s0 = (uint32_t)((r0 * 40 + o0) * 2);
    const uint32_t s1 = (uint32_t)((r1 * 40 + o1) * 2);

    constexpr int NIT = KTOT / 32;

#define ISSUE_STAGE(stg, itk) do {                                          \
        const uint32_t sb_ = base + (uint32_t)(stg) * STAGE_B;              \
        const int k0_ = (itk) * 32;                                         \
        cp16(sb_ + s0,          Ag + (size_t)r0 * KTOT + k0_ + o0);         \
        cp16(sb_ + SBUF_B + s0, Bg + (size_t)r0 * KTOT + k0_ + o0);         \
        cp16(sb_ + s1,          Ag + (size_t)r1 * KTOT + k0_ + o1);         \
        cp16(sb_ + SBUF_B + s1, Bg + (size_t)r1 * KTOT + k0_ + o1);         \
        asm volatile("cp.async.commit_group;" ::: "memory");                \
    } while (0)

    ISSUE_STAGE(0, 0);
    if (NIT > 1) ISSUE_STAGE(1, 1);

    for (int it = 0; it < NIT; it++) {
        if (it + 2 < NIT) {
            ISSUE_STAGE((it + 2) % 3, it + 2);
            asm volatile("cp.async.wait_group 2;" ::: "memory");
        } else if (it + 1 < NIT) {
            asm volatile("cp.async.wait_group 1;" ::: "memory");
        } else {
            asm volatile("cp.async.wait_group 0;" ::: "memory");
        }
        __syncthreads();
        const uint32_t ab = base + (uint32_t)((it % 3)) * STAGE_B;
        const uint32_t bb = ab + SBUF_B;
#pragma unroll
        for (int ks = 0; ks < 32; ks += 16) {
            uint32_t af[4][4], bf[4][2];
            const int ar = lane & 15, ac = ks + ((lane >> 4) << 3);
#pragma unroll
            for (int i = 0; i < 4; i++)
                ldsm_x4(af[i], ab + (uint32_t)(((wm * 64 + i * 16 + ar) * 40 + ac) << 1));
            const int l = lane & 15;
            const int br_ = l & 7, bc = ks + ((l >> 3) << 3);
#pragma unroll
            for (int j = 0; j < 4; j++)
                ldsm_x2(bf[j], bb + (uint32_t)(((wn * 32 + j * 8 + br_) * 40 + bc) << 1));
#pragma unroll
            for (int i = 0; i < 4; i++)
#pragma unroll
                for (int j = 0; j < 4; j++)
                    mma_f16(acc[i][j], af[i], bf[j]);
        }
        __syncthreads();
    }
#undef ISSUE_STAGE

#pragma unroll
    for (int i = 0; i < 4; i++) {
        const int row = wm * 64 + i * 16 + (lane >> 2);
#pragma unroll
        for (int j = 0; j < 4; j++) {
            const int col = wn * 32 + j * 8 + (lane & 3) * 2;
            epi(row,     col, acc[i][j][0], acc[i][j][1]);
            epi(row + 8, col, acc[i][j][2], acc[i][j][3]);
        }
    }
}

// ============================================================================
// Scores: S = Qcat @ Kcat^T * 1/16, K=512 fp16 ([hr|hi] both sides)
// ============================================================================
__global__ __launch_bounds__(256) void score_mma(
    const __half* __restrict__ Q, const __half* __restrict__ K,
    float* __restrict__ S)
{
    const int head = blockIdx.z;
    const int bm = blockIdx.x * 128, bn = blockIdx.y * 128;
    const uint16_t* A = (const uint16_t*)(Q + ((size_t)head * T_SEQ + bm) * KSC);
    const uint16_t* B = (const uint16_t*)(K + ((size_t)head * T_SEQ + bn) * KSC);
    float* C = S + ((size_t)head * T_SEQ + bm) * T_SEQ + bn;
    auto epi = [&](int r, int c, float v0, float v1) {
        *(float2*)(C + (size_t)r * T_SEQ + c) = make_float2(v0 * 0.0625f, v1 * 0.0625f);
    };
    gemm_mma_core<KSC>(A, B, epi);
}

// ============================================================================
// Context: attn @ Vt^T, fp16, K=2048. grid (16, 2, 64) z=head*2+part.
// Epilogue writes h/l split DIRECTLY into acat [M,1024]:
//   part=0 (real): h at +c, l at +256+c ; part=1 (imag): h at +512+c, l at +768+c
// ============================================================================
__global__ __launch_bounds__(256) void ctx_mma(
    const __half* __restrict__ Attn, const __half* __restrict__ Vtr,
    const __half* __restrict__ Vti, __half* __restrict__ Acat)
{
    const int bz = blockIdx.z;
    const int head = bz >> 1, part = bz & 1;
    const int bm = blockIdx.x * 128, bn = blockIdx.y * 128;
    const uint16_t* A = (const uint16_t*)(Attn + ((size_t)head * T_SEQ + bm) * T_SEQ);
    const __half* Vt = part ? Vti : Vtr;
    const uint16_t* B = (const uint16_t*)(Vt + ((size_t)head * D_MOD + bn) * T_SEQ);
    const size_t rbase = (size_t)head * T_SEQ + bm;
    const int hoff = part * 512;
    auto epi = [&](int r, int c, float v0, float v1) {
        uint32_t* out = (uint32_t*)(Acat + (rbase + r) * KCAT);
        float h0f = __half2float(__float2half_rn(v0));
        float h1f = __half2float(__float2half_rn(v1));
        const int gc = bn + c;
        out[(hoff + gc) >> 1]       = pack_h2(h0f, h1f);
        out[(hoff + 256 + gc) >> 1] = pack_h2(v0 - h0f, v1 - h1f);
    };
    gemm_mma_core<T_SEQ>(A, B, epi);
}

// ============================================================================
// q/k/v projection (fp16-cat output, K=512):
// A_cat [M,512] = [h(Ar)|h(Ai)], W_cat [512,512]:
//   rows 0-255  (Cr): [h(Wr)|h(-Wi)] ; rows 256-511(Ci): [h(Wi)|h(Wr)]
// Epilogue: +bias, fp16, write cat[row*512 + (i?256:0) + col]. grid (M/128, 4).
// ============================================================================
__global__ __launch_bounds__(256) void proj_h16_k512(
    const __half* __restrict__ Acat, const __half* __restrict__ Wcat,
    const float* __restrict__ bR, const float* __restrict__ bI,
    __half* __restrict__ Cat)
{
    const int bm = blockIdx.x * 128, bn = blockIdx.y * 128;
    const uint16_t* A = (const uint16_t*)(Acat + (size_t)bm * KSC);
    const uint16_t* B = (const uint16_t*)(Wcat + (size_t)bn * KSC);
    const float* bias = (bn >= 256) ? bI : bR;
    const int off = (bn >= 256) ? 256 + (bn & 255) : bn;
    auto epi = [&](int r, int c, float v0, float v1) {
        const int gc = (bn & 255) + c;
        *(uint32_t*)(Cat + (size_t)(bm + r) * KSC + off + c)
            = pack_h2(v0 + __ldg(bias + gc), v1 + __ldg(bias + gc + 1));
    };
    gemm_mma_core<KSC>(A, B, epi);
}

// ============================================================================
// o-projection (fp32 output, K=1024 h/l): +bias, write Cr/Ci. grid (M/128, 4).
// ============================================================================
__global__ __launch_bounds__(256) void proj_mma(
    const __half* __restrict__ Acat, const __half* __restrict__ Wcat,
    const float* __restrict__ bR, const float* __restrict__ bI,
    float* __restrict__ Cr, float* __restrict__ Ci)
{
    const int bm = blockIdx.x * 128, bn = blockIdx.y * 128;
    const uint16_t* A = (const uint16_t*)(Acat + (size_t)bm * KCAT);
    const uint16_t* B = (const uint16_t*)(Wcat + (size_t)bn * KCAT);
    float* Cbase = (bn >= 256) ? Ci : Cr;
    const float* bias = (bn >= 256) ? bI : bR;
    const int coff = bn & 255;
    auto epi = [&](int r, int c, float v0, float v1) {
        const int gc = coff + c;
        *(float2*)(Cbase + (size_t)(bm + r) * D_MOD + gc)
            = make_float2(v0 + __ldg(bias + gc), v1 + __ldg(bias + gc + 1));
    };
    gemm_mma_core<KCAT>(A, B, epi);
}

// ============================================================================
// Gate + finalize fused: G = sigmoid(magcat @ Wg^T + b); out = (Or*G, Oi*G)
// magcat [M,512] = [h(mag)|l(mag)], Wg [256,512]. grid (M/128, 2).
// ============================================================================
__global__ __launch_bounds__(256) void gate_mma(
    const __half* __restrict__ Mag, const __half* __restrict__ Wg,
    const float* __restrict__ bias,
    const float* __restrict__ Or, const float* __restrict__ Oi,
    float* __restrict__ out)
{
    const int bm = blockIdx.x * 128, bn = blockIdx.y * 128;
    const uint16_t* A = (const uint16_t*)(Mag + (size_t)bm * KSC);
    const uint16_t* B = (const uint16_t*)(Wg + (size_t)bn * KSC);
    auto epi = [&](int r, int c, float v0, float v1) {
        const int gc = bn + c;
        const size_t row = (size_t)(bm + r);
        float g0 = 1.f / (1.f + __expf(-(v0 + __ldg(bias + gc))));
        float g1 = 1.f / (1.f + __expf(-(v1 + __ldg(bias + gc + 1))));
        float2 a = *(const float2*)(Or + row * D_MOD + gc);
        float2 b = *(const float2*)(Oi + row * D_MOD + gc);
        *(float2*)(out + row * D_MOD + gc) = make_float2(a.x * g0, a.y * g1);
        *(float2*)(out + (size_t)M_TOT * D_MOD + row * D_MOD + gc)
            = make_float2(b.x * g0, b.y * g1);
    };
    gemm_mma_core<KSC>(A, B, epi);
}

// ============================================================================
// W_cat [512,512] fp16 for q/k/v. 256 blocks x 256 thr (4 floats each).
// ============================================================================
__global__ __launch_bounds__(256) void convert_wcat512(
    const float* __restrict__ Wr, const float* __restrict__ Wi,
    __half* __restrict__ Wcat)
{
    const int t = blockIdx.x * 256 + threadIdx.x;
    const int r = t >> 7;              /* 0..511 */
    const int c = (t & 127) * 4;       /* 0..508 */
    const int seg = c >> 8;            /* 0..1 */
    const int k = c & 255;
    const int m = r & 255;
    const float* src;
    float sign = 1.f;
    if (r < 256) { if (seg == 0) src = Wr; else { src = Wi; sign = -1.f; } }
    else         { src = (seg == 0) ? Wi : Wr; }
    float4 w = *(const float4*)(src + (size_t)m * 256 + k);
    uint32_t* out = (uint32_t*)(Wcat + (size_t)r * KSC + c);
    out[0] = pack_h2(sign * w.x, sign * w.y);
    out[1] = pack_h2(sign * w.z, sign * w.w);
}

// ============================================================================
// W_cat [512,1024] fp16 for o-projection (h/l input):
//   rows 0-255  (Cr): [h(Wr)|h(Wr)|h(-Wi)|h(-Wi)]
//   rows 256-511(Ci): [h(Wi)|h(Wi)|h(Wr) |h(Wr) ]
// ============================================================================
__global__ __launch_bounds__(256) void convert_wcat(
    const float* __restrict__ Wr, const float* __restrict__ Wi,
    __half* __restrict__ Wcat)
{
    const int t = blockIdx.x * 256 + threadIdx.x;
    const int r = t >> 8;
    const int c = (t & 255) * 4;
    const int seg = c >> 8;
    const int k = c & 255;
    const int m = r & 255;
    const float* src;
    float sign = 1.f;
    if (r < 256) { if (seg < 2) src = Wr; else { src = Wi; sign = -1.f; } }
    else         { src = (seg < 2) ? Wi : Wr; }
    float4 w = *(const float4*)(src + (size_t)m * 256 + k);
    uint32_t* out = (uint32_t*)(Wcat + (size_t)r * KCAT + c);
    out[0] = pack_h2(sign * w.x, sign * w.y);
    out[1] = pack_h2(sign * w.z, sign * w.w);
}

// Gate weight cat [256,512] = [h(W)|h(W)]. 128 blocks x 256 thr.
__global__ __launch_bounds__(256) void convert_wgate(
    const float* __restrict__ W, __half* __restrict__ Wg)
{
    const int t = blockIdx.x * 256 + threadIdx.x;
    const int r = t >> 7;
    const int c = (t & 127) * 4;
    const int k = c & 255;
    float4 w = *(const float4*)(W + (size_t)r * 256 + k);
    uint32_t* out = (uint32_t*)(Wg + (size_t)r * KSC + c);
    out[0] = pack_h2(w.x, w.y);
    out[1] = pack_h2(w.z, w.w);
}

// ============================================================================
// Input conversion -> row of 512 fp16 [h(r)|h(i)] (no lo segments).
// ============================================================================
__global__ __launch_bounds__(256) void convert_h512(
    const float* __restrict__ Xr, const float* __restrict__ Xi,
    __half* __restrict__ cat)
{
    const size_t t = (size_t)blockIdx.x * 256 + threadIdx.x;
    const size_t row = t >> 6;
    const int c = (int)(t & 63) << 2;
    float4 xr = *(const float4*)(Xr + row*256 + c);
    float4 xi = *(const float4*)(Xi + row*256 + c);
    uint32_t* out = (uint32_t*)(cat + row * KSC);
    const int c2 = c >> 1;
    out[c2]         = pack_h2(xr.x, xr.y); out[c2+1]       = pack_h2(xr.z, xr.w);
    out[128 + c2]   = pack_h2(xi.x, xi.y); out[128 + c2+1] = pack_h2(xi.z, xi.w);
}

// ============================================================================
// Mag split: outr/outi fp32 -> magcat [M,512] = [h(mag)|l(mag)]
// ============================================================================
__global__ __launch_bounds__(256) void convert_mag(
    const float* __restrict__ Or, const float* __restrict__ Oi,
    __half* __restrict__ Mag)
{
    const size_t t = (size_t)blockIdx.x * 256 + threadIdx.x;
    const size_t row = t >> 6;
    const int c = (int)(t & 63) << 2;
    float4 a = *(const float4*)(Or + row*256 + c);
    float4 b = *(const float4*)(Oi + row*256 + c);
    float m[4] = {sqrtf(a.x*a.x + b.x*b.x + EPS_F), sqrtf(a.y*a.y + b.y*b.y + EPS_F),
                  sqrtf(a.z*a.z + b.z*b.z + EPS_F), sqrtf(a.w*a.w + b.w*b.w + EPS_F)};
    float h[4], l[4];
#pragma unroll
    for (int j = 0; j < 4; j++) {
        __half hh = __float2half_rn(m[j]);
        h[j] = __half2float(hh); l[j] = m[j] - h[j];
    }
    uint32_t* out = (uint32_t*)(Mag + row * KSC);
    const int c2 = c >> 1;
    out[c2]         = pack_h2(h[0], h[1]); out[c2+1]       = pack_h2(h[2], h[3]);
    out[128 + c2]   = pack_h2(l[0], l[1]); out[128 + c2+1] = pack_h2(l[2], l[3]);
}

// ============================================================================
// Transpose V: vcat fp16 [bh*T_SEQ][512]([hr|hi]) -> Vt[bh][n=256][k=2048] fp16
// ============================================================================
__global__ void transpose_v(
    const __half* __restrict__ Vcat,
    __half* __restrict__ Vtr, __half* __restrict__ Vti)
{
    __shared__ __half tr[32][33], ti[32][33];
    const int head = blockIdx.z;
    const int k0 = blockIdx.x * 32, n0 = blockIdx.y * 32;
    const int tx = threadIdx.x, ty = threadIdx.y;
    const size_t ibase = (size_t)head * T_SEQ;
#pragma unroll
    for (int i = 0; i < 32; i += 8) {
        const __half* src = Vcat + (ibase + k0 + ty + i) * KSC;
        tr[ty+i][tx] = src[n0 + tx];
        ti[ty+i][tx] = src[256 + n0 + tx];
    }
    __syncthreads();
    const size_t obase = ((size_t)head * 256 + n0) * T_SEQ + k0;
#pragma unroll
    for (int i = 0; i < 32; i += 8) {
        Vtr[obase + (size_t)(ty+i)*T_SEQ + tx] = tr[tx][ty+i];
        Vti[obase + (size_t)(ty+i)*T_SEQ + tx] = ti[tx][ty+i];
    }
}

// ============================================================================
// Row softmax: read fp32 scores, write fp16 attn
// ============================================================================
__global__ __launch_bounds__(256) void softmax_rows(
    const float* __restrict__ S, __half* __restrict__ A)
{
    const float* p = S + (size_t)blockIdx.x * T_SEQ;
    __half* ap = A + (size_t)blockIdx.x * T_SEQ;
    const int tid = threadIdx.x;
    float v[8];
    float m = -3.4e38f;
#pragma unroll
    for (int r = 0; r < 8; r++) { v[r] = p[tid + (r << 8)]; m = fmaxf(m, v[r]); }
#pragma unroll
    for (int o = 16; o > 0; o >>= 1) m = fmaxf(m, __shfl_xor_sync(0xffffffffu, m, o));
    __shared__ float red[8];
    if ((tid & 31) == 0) red[tid >> 5] = m;
    __syncthreads();
    m = red[0];
#pragma unroll
    for (int w = 1; w < 8; w++) m = fmaxf(m, red[w]);
    float sum = 0.f;
#pragma unroll
    for (int r = 0; r < 8; r++) { v[r] = __expf(v[r] - m); sum += v[r]; }
#pragma unroll
    for (int o = 16; o > 0; o >>= 1) sum += __shfl_xor_sync(0xffffffffu, sum, o);
    __syncthreads();
    if ((tid & 31) == 0) red[tid >> 5] = sum;
    __syncthreads();
    sum = 0.f;
#pragma unroll
    for (int w = 0; w < 8; w++) sum += red[w];
    const float inv = 1.f / sum;
#pragma unroll
    for (int r = 0; r < 8; r++) ap[tid + (r << 8)] = __float2half(v[r] * inv);
}

// ============================================================================
extern "C" void kernel_launch(void* const* d_in, const int* in_sizes, int n_in,
                              void* d_out, int out_size)
{
    const float* q_in_r  = (const float*)d_in[0];
    const float* q_in_i  = (const float*)d_in[1];
    const float* kv_in_r = (const float*)d_in[2];
    const float* kv_in_i = (const float*)d_in[3];
    const float* q_wr = (const float*)d_in[4];
    const float* q_wi = (const float*)d_in[5];
    const float* q_br = (const float*)d_in[6];
    const float* q_bi = (const float*)d_in[7];
    const float* k_wr = (const float*)d_in[8];
    const float* k_wi = (const float*)d_in[9];
    const float* k_br = (const float*)d_in[10];
    const float* k_bi = (const float*)d_in[11];
    const float* v_wr = (const float*)d_in[12];
    const float* v_wi = (const float*)d_in[13];
    const float* v_br = (const float*)d_in[14];
    const float* v_bi = (const float*)d_in[15];
    const float* o_wr = (const float*)d_in[16];
    const float* o_wi = (const float*)d_in[17];
    const float* o_br = (const float*)d_in[18];
    const float* o_bi = (const float*)d_in[19];
    const float* gate_w = (const float*)d_in[20];
    const float* gate_b = (const float*)d_in[21];

    float *p_or, *p_oi, *p_sc;
    __half *p_attn, *p_vtr, *p_vti, *p_qcat, *p_kcat, *p_vcat;
    __half *p_acat1, *p_acat2, *p_acat3;
    __half *p_wq, *p_wk, *p_wv, *p_wo, *p_wg;
    cudaGetSymbolAddress((void**)&p_or, g_outr);
    cudaGetSymbolAddress((void**)&p_oi, g_outi);
    cudaGetSymbolAddress((void**)&p_sc, g_sc);
    cudaGetSymbolAddress((void**)&p_attn, g_attn);
    cudaGetSymbolAddress((void**)&p_qcat, g_qcat);
    cudaGetSymbolAddress((void**)&p_kcat, g_kcat);
    cudaGetSymbolAddress((void**)&p_vcat, g_vcat);
    cudaGetSymbolAddress((void**)&p_acat1, g_acat1);
    cudaGetSymbolAddress((void**)&p_acat2, g_acat2);
    cudaGetSymbolAddress((void**)&p_acat3, g_acat3);
    cudaGetSymbolAddress((void**)&p_vtr, g_vtr);
    cudaGetSymbolAddress((void**)&p_vti, g_vti);
    cudaGetSymbolAddress((void**)&p_wq, g_wq);
    cudaGetSymbolAddress((void**)&p_wk, g_wk);
    cudaGetSymbolAddress((void**)&p_wv, g_wv);
    cudaGetSymbolAddress((void**)&p_wo, g_wo);
    cudaGetSymbolAddress((void**)&p_wg, g_wg);

    cudaFuncSetAttribute(score_mma, cudaFuncAttributeMaxDynamicSharedMemorySize, 61440);
    cudaFuncSetAttribute(ctx_mma,   cudaFuncAttributeMaxDynamicSharedMemorySize, 61440);
    cudaFuncSetAttribute(proj_mma,  cudaFuncAttributeMaxDynamicSharedMemorySize, 61440);
    cudaFuncSetAttribute(proj_h16_k512, cudaFuncAttributeMaxDynamicSharedMemorySize, 61440);
    cudaFuncSetAttribute(gate_mma,  cudaFuncAttributeMaxDynamicSharedMemorySize, 61440);

    const dim3 tpb(256);
    const dim3 proj_grid(M_TOT / 128, 4);

    // Input cats (K=512, h only) + weight cats
    convert_h512<<<16384, tpb>>>(q_in_r, q_in_i, p_acat1);
    convert_h512<<<16384, tpb>>>(kv_in_r, kv_in_i, p_acat2);
    convert_wcat512<<<256, tpb>>>(q_wr, q_wi, p_wq);
    convert_wcat512<<<256, tpb>>>(k_wr, k_wi, p_wk);
    convert_wcat512<<<256, tpb>>>(v_wr, v_wi, p_wv);
    convert_wcat<<<512, tpb>>>(o_wr, o_wi, p_wo);
    convert_wgate<<<128, tpb>>>(gate_w, p_wg);

    // q/k/v projections (K=512) -> fp16 cats directly
    proj_h16_k512<<<proj_grid, tpb, 61440>>>(p_acat1, p_wq, q_br, q_bi, p_qcat);
    proj_h16_k512<<<proj_grid, tpb, 61440>>>(p_acat2, p_wk, k_br, k_bi, p_kcat);
    proj_h16_k512<<<proj_grid, tpb, 61440>>>(p_acat2, p_wv, v_br, v_bi, p_vcat);
    transpose_v<<<dim3(T_SEQ/32, D_MOD/32, N_BH), dim3(32, 8)>>>(p_vcat, p_vtr, p_vti);

    // Attention
    score_mma<<<dim3(16, 16, N_BH), tpb, 61440>>>(p_qcat, p_kcat, p_sc);
    softmax_rows<<<(unsigned)(N_BH * T_SEQ), tpb>>>(p_sc, p_attn);
    // ctx writes o-proj h/l acat directly
    ctx_mma<<<dim3(16, 2, 2 * N_BH), tpb, 61440>>>(p_attn, p_vtr, p_vti, p_acat3);

    // Output projection (fp32 out, K=1024) + fused gate/finalize
    proj_mma<<<proj_grid, tpb, 61440>>>(p_acat3, p_wo, o_br, o_bi, p_or, p_oi);
    convert_mag<<<16384, tpb>>>(p_or, p_oi, p_qcat);   // reuse qcat as magcat
    gate_mma<<<dim3(M_TOT / 128, 2), tpb, 61440>>>(p_qcat, p_wg, gate_b,
                                                   p_or, p_oi, (float*)d_out);
}

// round 16
// speedup vs baseline: 1.2822x; 1.2822x over previous
#include <cuda_runtime.h>
#include <cuda_bf16.h>
#include <cuda_fp16.h>
#include <math.h>
#include <stdint.h>

#define T_SEQ 2048
#define D_MOD 256
#define N_BH  32
#define M_TOT (N_BH * T_SEQ)   /* 65536 */
#define EPS_F 1e-8f
#define KCAT  1024              /* split-fp16 K for projections */
#define KSC   512               /* fp16 K for scores / gate */

// ---- scratch (device globals; no runtime allocation allowed) ----
__device__ float g_outr[M_TOT * D_MOD];
__device__ float g_outi[M_TOT * D_MOD];
__device__ float g_sc[(size_t)N_BH * T_SEQ * T_SEQ];          /* 512 MB fp32 scores */
__device__ __half g_attn[(size_t)N_BH * T_SEQ * T_SEQ];       /* 256 MB fp16 attn  */
__device__ __half g_qcat[(size_t)M_TOT * KSC];                /* 64 MB  [hr|hi] / magcat */
__device__ __half g_kcat[(size_t)M_TOT * KSC];                /* 64 MB  [hr|hi]    */
__device__ __half g_vcat[(size_t)M_TOT * KSC];                /* 64 MB  [hr|hi]    */
__device__ __half g_acat1[(size_t)M_TOT * KCAT];              /* 128 MB q input acat */
__device__ __half g_acat2[(size_t)M_TOT * KCAT];              /* 128 MB kv acat / ctx acat */
__device__ __half g_vtr[(size_t)N_BH * D_MOD * T_SEQ];        /* 32 MB V^T fp16    */
__device__ __half g_vti[(size_t)N_BH * D_MOD * T_SEQ];        /* 32 MB V^T fp16    */
__device__ __half g_wq[512 * KCAT];                           /* 1 MB weight cat   */
__device__ __half g_wk[512 * KCAT];
__device__ __half g_wv[512 * KCAT];
__device__ __half g_wo[512 * KCAT];
__device__ __half g_wg[256 * KSC];                            /* gate W cat        */

// ============================================================================
// helpers
// ============================================================================
__device__ __forceinline__ uint32_t smem_to_u32(const void* smem_ptr) {
    uint32_t addr;
    asm("{ .reg .u64 tmp; cvta.to.shared.u64 tmp, %1; cvt.u32.u64 %0, tmp; }"
        : "=r"(addr) : "l"(smem_ptr));
    return addr;
}
__device__ __forceinline__ void cp16(uint32_t smem_addr, const void* gptr) {
    asm volatile("cp.async.cg.shared.global [%0], [%1], 16;"
                 :: "r"(smem_addr), "l"(gptr) : "memory");
}
__device__ __forceinline__ void ldsm_x4(uint32_t* r, uint32_t addr) {
    asm volatile("ldmatrix.sync.aligned.m8n8.x4.shared.b16 {%0,%1,%2,%3}, [%4];"
                 : "=r"(r[0]), "=r"(r[1]), "=r"(r[2]), "=r"(r[3]) : "r"(addr));
}
__device__ __forceinline__ void ldsm_x2(uint32_t* r, uint32_t addr) {
    asm volatile("ldmatrix.sync.aligned.m8n8.x2.shared.b16 {%0,%1}, [%2];"
                 : "=r"(r[0]), "=r"(r[1]) : "r"(addr));
}
__device__ __forceinline__ void mma_f16(float* d, const uint32_t* a, const uint32_t* b) {
    asm volatile(
        "mma.sync.aligned.m16n8k16.row.col.f32.f16.f16.f32 "
        "{%0,%1,%2,%3}, {%4,%5,%6,%7}, {%8,%9}, {%0,%1,%2,%3};"
        : "+f"(d[0]), "+f"(d[1]), "+f"(d[2]), "+f"(d[3])
        : "r"(a[0]), "r"(a[1]), "r"(a[2]), "r"(a[3]), "r"(b[0]), "r"(b[1]));
}
__device__ __forceinline__ uint32_t pack_h2(float a, float b) {
    __half2 t = __floats2half2_rn(a, b);
    return *(uint32_t*)&t;
}

// ============================================================================
// Core 128x128 NT tile GEMM on mma.sync fp16 (A,B K-major), fp32 accum.
// 256 threads = 8 warps in 2(m) x 4(n); warp tile 64x32; Kblk=32.
// 3-stage cp.async pipeline in dynamic smem (61440 B).
// Epilogue callback: epi(row, col, v0, v1).
// ============================================================================
#define SBUF_B   10240u
#define STAGE_B  20480u

template<int KTOT, typename Epi>
__device__ __forceinline__ void gemm_mma_core(
    const uint16_t* __restrict__ Ag, const uint16_t* __restrict__ Bg, Epi epi)
{
    extern __shared__ uint16_t sh16[];
    const uint32_t base = smem_to_u32(sh16);
    const int tid = threadIdx.x;
    const int wid = tid >> 5, lane = tid & 31;
    const int wm = wid & 1, wn = wid >> 1;

    float acc[4][4][4];
#pragma unroll
    for (int i = 0; i < 4; i++)
#pragma unroll
        for (int j = 0; j < 4; j++)
#pragma unroll
            for (int v = 0; v < 4; v++) acc[i][j][v] = 0.f;

    const int c0 = tid, c1 = tid + 256;
    const int r0 = c0 >> 2, o0 = (c0 & 3) * 8;
    const int r1 = c1 >> 2, o1 = (c1 & 3) * 8;
    const uint32_t s0 = (uint32_t)((r0 * 40 + o0) * 2);
    const uint32_t s1 = (uint32_t)((r1 * 40 + o1) * 2);

    constexpr int NIT = KTOT / 32;

#define ISSUE_STAGE(stg, itk) do {                                          \
        const uint32_t sb_ = base + (uint32_t)(stg) * STAGE_B;              \
        const int k0_ = (itk) * 32;                                         \
        cp16(sb_ + s0,          Ag + (size_t)r0 * KTOT + k0_ + o0);         \
        cp16(sb_ + SBUF_B + s0, Bg + (size_t)r0 * KTOT + k0_ + o0);         \
        cp16(sb_ + s1,          Ag + (size_t)r1 * KTOT + k0_ + o1);         \
        cp16(sb_ + SBUF_B + s1, Bg + (size_t)r1 * KTOT + k0_ + o1);         \
        asm volatile("cp.async.commit_group;" ::: "memory");                \
    } while (0)

    ISSUE_STAGE(0, 0);
    if (NIT > 1) ISSUE_STAGE(1, 1);

    for (int it = 0; it < NIT; it++) {
        if (it + 2 < NIT) {
            ISSUE_STAGE((it + 2) % 3, it + 2);
            asm volatile("cp.async.wait_group 2;" ::: "memory");
        } else if (it + 1 < NIT) {
            asm volatile("cp.async.wait_group 1;" ::: "memory");
        } else {
            asm volatile("cp.async.wait_group 0;" ::: "memory");
        }
        __syncthreads();
        const uint32_t ab = base + (uint32_t)((it % 3)) * STAGE_B;
        const uint32_t bb = ab + SBUF_B;
#pragma unroll
        for (int ks = 0; ks < 32; ks += 16) {
            uint32_t af[4][4], bf[4][2];
            const int ar = lane & 15, ac = ks + ((lane >> 4) << 3);
#pragma unroll
            for (int i = 0; i < 4; i++)
                ldsm_x4(af[i], ab + (uint32_t)(((wm * 64 + i * 16 + ar) * 40 + ac) << 1));
            const int l = lane & 15;
            const int br_ = l & 7, bc = ks + ((l >> 3) << 3);
#pragma unroll
            for (int j = 0; j < 4; j++)
                ldsm_x2(bf[j], bb + (uint32_t)(((wn * 32 + j * 8 + br_) * 40 + bc) << 1));
#pragma unroll
            for (int i = 0; i < 4; i++)
#pragma unroll
                for (int j = 0; j < 4; j++)
                    mma_f16(acc[i][j], af[i], bf[j]);
        }
        __syncthreads();
    }
#undef ISSUE_STAGE

#pragma unroll
    for (int i = 0; i < 4; i++) {
        const int row = wm * 64 + i * 16 + (lane >> 2);
#pragma unroll
        for (int j = 0; j < 4; j++) {
            const int col = wn * 32 + j * 8 + (lane & 3) * 2;
            epi(row,     col, acc[i][j][0], acc[i][j][1]);
            epi(row + 8, col, acc[i][j][2], acc[i][j][3]);
        }
    }
}

// ============================================================================
// Scores: S = Qcat @ Kcat^T * 1/16, K=512 fp16 ([hr|hi] both sides)
// ============================================================================
__global__ __launch_bounds__(256) void score_mma(
    const __half* __restrict__ Q, const __half* __restrict__ K,
    float* __restrict__ S)
{
    const int head = blockIdx.z;
    const int bm = blockIdx.x * 128, bn = blockIdx.y * 128;
    const uint16_t* A = (const uint16_t*)(Q + ((size_t)head * T_SEQ + bm) * KSC);
    const uint16_t* B = (const uint16_t*)(K + ((size_t)head * T_SEQ + bn) * KSC);
    float* C = S + ((size_t)head * T_SEQ + bm) * T_SEQ + bn;
    auto epi = [&](int r, int c, float v0, float v1) {
        *(float2*)(C + (size_t)r * T_SEQ + c) = make_float2(v0 * 0.0625f, v1 * 0.0625f);
    };
    gemm_mma_core<KSC>(A, B, epi);
}

// ============================================================================
// Context: attn @ Vt^T, fp16, K=2048. grid (16, 2, 64) z=head*2+part.
// Epilogue writes h/l split DIRECTLY into acat [M,1024]:
//   part=0 (real): h at +c, l at +256+c ; part=1 (imag): h at +512+c, l at +768+c
// ============================================================================
__global__ __launch_bounds__(256) void ctx_mma(
    const __half* __restrict__ Attn, const __half* __restrict__ Vtr,
    const __half* __restrict__ Vti, __half* __restrict__ Acat)
{
    const int bz = blockIdx.z;
    const int head = bz >> 1, part = bz & 1;
    const int bm = blockIdx.x * 128, bn = blockIdx.y * 128;
    const uint16_t* A = (const uint16_t*)(Attn + ((size_t)head * T_SEQ + bm) * T_SEQ);
    const __half* Vt = part ? Vti : Vtr;
    const uint16_t* B = (const uint16_t*)(Vt + ((size_t)head * D_MOD + bn) * T_SEQ);
    const size_t rbase = (size_t)head * T_SEQ + bm;
    const int hoff = part * 512;
    auto epi = [&](int r, int c, float v0, float v1) {
        uint32_t* out = (uint32_t*)(Acat + (rbase + r) * KCAT);
        float h0f = __half2float(__float2half_rn(v0));
        float h1f = __half2float(__float2half_rn(v1));
        const int gc = bn + c;
        out[(hoff + gc) >> 1]       = pack_h2(h0f, h1f);
        out[(hoff + 256 + gc) >> 1] = pack_h2(v0 - h0f, v1 - h1f);
    };
    gemm_mma_core<T_SEQ>(A, B, epi);
}

// ============================================================================
// Projection (fp16-cat output, for q/k/v):
// A_cat [M,1024] = [h(Ar)|l(Ar)|h(Ai)|l(Ai)], W_cat [512,1024] (see convert_wcat).
// Epilogue: +bias, convert to fp16, write cat[row*512 + (i?256:0) + col].
// grid (M/128, 4).
// ============================================================================
__global__ __launch_bounds__(256) void proj_h16(
    const __half* __restrict__ Acat, const __half* __restrict__ Wcat,
    const float* __restrict__ bR, const float* __restrict__ bI,
    __half* __restrict__ Cat)
{
    const int bm = blockIdx.x * 128, bn = blockIdx.y * 128;
    const uint16_t* A = (const uint16_t*)(Acat + (size_t)bm * KCAT);
    const uint16_t* B = (const uint16_t*)(Wcat + (size_t)bn * KCAT);
    const float* bias = (bn >= 256) ? bI : bR;
    const int off = (bn >= 256) ? 256 + (bn & 255) : bn;
    auto epi = [&](int r, int c, float v0, float v1) {
        const int gc = (bn & 255) + c;
        *(uint32_t*)(Cat + (size_t)(bm + r) * KSC + off + c)
            = pack_h2(v0 + __ldg(bias + gc), v1 + __ldg(bias + gc + 1));
    };
    gemm_mma_core<KCAT>(A, B, epi);
}

// ============================================================================
// Projection (fp32 output, for o): +bias, write Cr/Ci. grid (M/128, 4).
// ============================================================================
__global__ __launch_bounds__(256) void proj_mma(
    const __half* __restrict__ Acat, const __half* __restrict__ Wcat,
    const float* __restrict__ bR, const float* __restrict__ bI,
    float* __restrict__ Cr, float* __restrict__ Ci)
{
    const int bm = blockIdx.x * 128, bn = blockIdx.y * 128;
    const uint16_t* A = (const uint16_t*)(Acat + (size_t)bm * KCAT);
    const uint16_t* B = (const uint16_t*)(Wcat + (size_t)bn * KCAT);
    float* Cbase = (bn >= 256) ? Ci : Cr;
    const float* bias = (bn >= 256) ? bI : bR;
    const int coff = bn & 255;
    auto epi = [&](int r, int c, float v0, float v1) {
        const int gc = coff + c;
        *(float2*)(Cbase + (size_t)(bm + r) * D_MOD + gc)
            = make_float2(v0 + __ldg(bias + gc), v1 + __ldg(bias + gc + 1));
    };
    gemm_mma_core<KCAT>(A, B, epi);
}

// ============================================================================
// Gate + finalize fused: G = sigmoid(magcat @ Wg^T + b); out = (Or*G, Oi*G)
// magcat [M,512] = [h(mag)|l(mag)], Wg [256,512]. grid (M/128, 2).
// ============================================================================
__global__ __launch_bounds__(256) void gate_mma(
    const __half* __restrict__ Mag, const __half* __restrict__ Wg,
    const float* __restrict__ bias,
    const float* __restrict__ Or, const float* __restrict__ Oi,
    float* __restrict__ out)
{
    const int bm = blockIdx.x * 128, bn = blockIdx.y * 128;
    const uint16_t* A = (const uint16_t*)(Mag + (size_t)bm * KSC);
    const uint16_t* B = (const uint16_t*)(Wg + (size_t)bn * KSC);
    auto epi = [&](int r, int c, float v0, float v1) {
        const int gc = bn + c;
        const size_t row = (size_t)(bm + r);
        float g0 = 1.f / (1.f + __expf(-(v0 + __ldg(bias + gc))));
        float g1 = 1.f / (1.f + __expf(-(v1 + __ldg(bias + gc + 1))));
        float2 a = *(const float2*)(Or + row * D_MOD + gc);
        float2 b = *(const float2*)(Oi + row * D_MOD + gc);
        *(float2*)(out + row * D_MOD + gc) = make_float2(a.x * g0, a.y * g1);
        *(float2*)(out + (size_t)M_TOT * D_MOD + row * D_MOD + gc)
            = make_float2(b.x * g0, b.y * g1);
    };
    gemm_mma_core<KSC>(A, B, epi);
}

// ============================================================================
// Build W_cat [512,1024] fp16 from Wr, Wi [256,256] fp32. grid 512 x 256 thr.
//   rows 0-255  (Cr): [h(Wr)|h(Wr)|h(-Wi)|h(-Wi)]
//   rows 256-511(Ci): [h(Wi)|h(Wi)|h(Wr) |h(Wr) ]
// ============================================================================
__global__ __launch_bounds__(256) void convert_wcat(
    const float* __restrict__ Wr, const float* __restrict__ Wi,
    __half* __restrict__ Wcat)
{
    const int t = blockIdx.x * 256 + threadIdx.x;
    const int r = t >> 8;
    const int c = (t & 255) * 4;
    const int seg = c >> 8;
    const int k = c & 255;
    const int m = r & 255;
    const float* src;
    float sign = 1.f;
    if (r < 256) { if (seg < 2) src = Wr; else { src = Wi; sign = -1.f; } }
    else         { src = (seg < 2) ? Wi : Wr; }
    float4 w = *(const float4*)(src + (size_t)m * 256 + k);
    uint32_t* out = (uint32_t*)(Wcat + (size_t)r * KCAT + c);
    out[0] = pack_h2(sign * w.x, sign * w.y);
    out[1] = pack_h2(sign * w.z, sign * w.w);
}

// Gate weight cat [256,512] = [h(W)|h(W)]. 128 blocks x 256 thr.
__global__ __launch_bounds__(256) void convert_wgate(
    const float* __restrict__ W, __half* __restrict__ Wg)
{
    const int t = blockIdx.x * 256 + threadIdx.x;
    const int r = t >> 7;
    const int c = (t & 127) * 4;
    const int k = c & 255;
    float4 w = *(const float4*)(W + (size_t)r * 256 + k);
    uint32_t* out = (uint32_t*)(Wg + (size_t)r * KSC + c);
    out[0] = pack_h2(w.x, w.y);
    out[1] = pack_h2(w.z, w.w);
}

// ============================================================================
// Input split-fp16 conversion -> row of 1024 fp16 [h(r)|l(r)|h(i)|l(i)].
// ============================================================================
__global__ __launch_bounds__(256) void convert_split(
    const float* __restrict__ Xr, const float* __restrict__ Xi,
    __half* __restrict__ cat)
{
    const size_t t = (size_t)blockIdx.x * 256 + threadIdx.x;
    const size_t row = t >> 6;
    const int c = (int)(t & 63) << 2;
    float4 xr = *(const float4*)(Xr + row*256 + c);
    float4 xi = *(const float4*)(Xi + row*256 + c);
    float vr[4] = {xr.x, xr.y, xr.z, xr.w};
    float vi[4] = {xi.x, xi.y, xi.z, xi.w};
    float hr[4], lr[4], hi[4], li[4];
#pragma unroll
    for (int j = 0; j < 4; j++) {
        __half h = __float2half_rn(vr[j]);
        hr[j] = __half2float(h); lr[j] = vr[j] - hr[j];
        __half g = __float2half_rn(vi[j]);
        hi[j] = __half2float(g); li[j] = vi[j] - hi[j];
    }
    uint32_t* out = (uint32_t*)(cat + row * KCAT);
    const int c2 = c >> 1;
    out[c2]         = pack_h2(hr[0], hr[1]); out[c2+1]       = pack_h2(hr[2], hr[3]);
    out[128 + c2]   = pack_h2(lr[0], lr[1]); out[128 + c2+1] = pack_h2(lr[2], lr[3]);
    out[256 + c2]   = pack_h2(hi[0], hi[1]); out[256 + c2+1] = pack_h2(hi[2], hi[3]);
    out[384 + c2]   = pack_h2(li[0], li[1]); out[384 + c2+1] = pack_h2(li[2], li[3]);
}

// ============================================================================
// Mag split: outr/outi fp32 -> magcat [M,512] = [h(mag)|l(mag)]
// ============================================================================
__global__ __launch_bounds__(256) void convert_mag(
    const float* __restrict__ Or, const float* __restrict__ Oi,
    __half* __restrict__ Mag)
{
    const size_t t = (size_t)blockIdx.x * 256 + threadIdx.x;
    const size_t row = t >> 6;
    const int c = (int)(t & 63) << 2;
    float4 a = *(const float4*)(Or + row*256 + c);
    float4 b = *(const float4*)(Oi + row*256 + c);
    float m[4] = {sqrtf(a.x*a.x + b.x*b.x + EPS_F), sqrtf(a.y*a.y + b.y*b.y + EPS_F),
                  sqrtf(a.z*a.z + b.z*b.z + EPS_F), sqrtf(a.w*a.w + b.w*b.w + EPS_F)};
    float h[4], l[4];
#pragma unroll
    for (int j = 0; j < 4; j++) {
        __half hh = __float2half_rn(m[j]);
        h[j] = __half2float(hh); l[j] = m[j] - h[j];
    }
    uint32_t* out = (uint32_t*)(Mag + row * KSC);
    const int c2 = c >> 1;
    out[c2]         = pack_h2(h[0], h[1]); out[c2+1]       = pack_h2(h[2], h[3]);
    out[128 + c2]   = pack_h2(l[0], l[1]); out[128 + c2+1] = pack_h2(l[2], l[3]);
}

// ============================================================================
// Transpose V: vcat fp16 [bh*T_SEQ][512]([hr|hi]) -> Vt[bh][n=256][k=2048] fp16
// ============================================================================
__global__ void transpose_v(
    const __half* __restrict__ Vcat,
    __half* __restrict__ Vtr, __half* __restrict__ Vti)
{
    __shared__ __half tr[32][33], ti[32][33];
    const int head = blockIdx.z;
    const int k0 = blockIdx.x * 32, n0 = blockIdx.y * 32;
    const int tx = threadIdx.x, ty = threadIdx.y;
    const size_t ibase = (size_t)head * T_SEQ;
#pragma unroll
    for (int i = 0; i < 32; i += 8) {
        const __half* src = Vcat + (ibase + k0 + ty + i) * KSC;
        tr[ty+i][tx] = src[n0 + tx];
        ti[ty+i][tx] = src[256 + n0 + tx];
    }
    __syncthreads();
    const size_t obase = ((size_t)head * 256 + n0) * T_SEQ + k0;
#pragma unroll
    for (int i = 0; i < 32; i += 8) {
        Vtr[obase + (size_t)(ty+i)*T_SEQ + tx] = tr[tx][ty+i];
        Vti[obase + (size_t)(ty+i)*T_SEQ + tx] = ti[tx][ty+i];
    }
}

// ============================================================================
// Row softmax: read fp32 scores, write fp16 attn
// ============================================================================
__global__ __launch_bounds__(256) void softmax_rows(
    const float* __restrict__ S, __half* __restrict__ A)
{
    const float* p = S + (size_t)blockIdx.x * T_SEQ;
    __half* ap = A + (size_t)blockIdx.x * T_SEQ;
    const int tid = threadIdx.x;
    float v[8];
    float m = -3.4e38f;
#pragma unroll
    for (int r = 0; r < 8; r++) { v[r] = p[tid + (r << 8)]; m = fmaxf(m, v[r]); }
#pragma unroll
    for (int o = 16; o > 0; o >>= 1) m = fmaxf(m, __shfl_xor_sync(0xffffffffu, m, o));
    __shared__ float red[8];
    if ((tid & 31) == 0) red[tid >> 5] = m;
    __syncthreads();
    m = red[0];
#pragma unroll
    for (int w = 1; w < 8; w++) m = fmaxf(m, red[w]);
    float sum = 0.f;
#pragma unroll
    for (int r = 0; r < 8; r++) { v[r] = __expf(v[r] - m); sum += v[r]; }
#pragma unroll
    for (int o = 16; o > 0; o >>= 1) sum += __shfl_xor_sync(0xffffffffu, sum, o);
    __syncthreads();
    if ((tid & 31) == 0) red[tid >> 5] = sum;
    __syncthreads();
    sum = 0.f;
#pragma unroll
    for (int w = 0; w < 8; w++) sum += red[w];
    const float inv = 1.f / sum;
#pragma unroll
    for (int r = 0; r < 8; r++) ap[tid + (r << 8)] = __float2half(v[r] * inv);
}

// ============================================================================
extern "C" void kernel_launch(void* const* d_in, const int* in_sizes, int n_in,
                              void* d_out, int out_size)
{
    const float* q_in_r  = (const float*)d_in[0];
    const float* q_in_i  = (const float*)d_in[1];
    const float* kv_in_r = (const float*)d_in[2];
    const float* kv_in_i = (const float*)d_in[3];
    const float* q_wr = (const float*)d_in[4];
    const float* q_wi = (const float*)d_in[5];
    const float* q_br = (const float*)d_in[6];
    const float* q_bi = (const float*)d_in[7];
    const float* k_wr = (const float*)d_in[8];
    const float* k_wi = (const float*)d_in[9];
    const float* k_br = (const float*)d_in[10];
    const float* k_bi = (const float*)d_in[11];
    const float* v_wr = (const float*)d_in[12];
    const float* v_wi = (const float*)d_in[13];
    const float* v_br = (const float*)d_in[14];
    const float* v_bi = (const float*)d_in[15];
    const float* o_wr = (const float*)d_in[16];
    const float* o_wi = (const float*)d_in[17];
    const float* o_br = (const float*)d_in[18];
    const float* o_bi = (const float*)d_in[19];
    const float* gate_w = (const float*)d_in[20];
    const float* gate_b = (const float*)d_in[21];

    float *p_or, *p_oi, *p_sc;
    __half *p_attn, *p_vtr, *p_vti, *p_qcat, *p_kcat, *p_vcat, *p_acat1, *p_acat2;
    __half *p_wq, *p_wk, *p_wv, *p_wo, *p_wg;
    cudaGetSymbolAddress((void**)&p_or, g_outr);
    cudaGetSymbolAddress((void**)&p_oi, g_outi);
    cudaGetSymbolAddress((void**)&p_sc, g_sc);
    cudaGetSymbolAddress((void**)&p_attn, g_attn);
    cudaGetSymbolAddress((void**)&p_qcat, g_qcat);
    cudaGetSymbolAddress((void**)&p_kcat, g_kcat);
    cudaGetSymbolAddress((void**)&p_vcat, g_vcat);
    cudaGetSymbolAddress((void**)&p_acat1, g_acat1);
    cudaGetSymbolAddress((void**)&p_acat2, g_acat2);
    cudaGetSymbolAddress((void**)&p_vtr, g_vtr);
    cudaGetSymbolAddress((void**)&p_vti, g_vti);
    cudaGetSymbolAddress((void**)&p_wq, g_wq);
    cudaGetSymbolAddress((void**)&p_wk, g_wk);
    cudaGetSymbolAddress((void**)&p_wv, g_wv);
    cudaGetSymbolAddress((void**)&p_wo, g_wo);
    cudaGetSymbolAddress((void**)&p_wg, g_wg);

    cudaFuncSetAttribute(score_mma, cudaFuncAttributeMaxDynamicSharedMemorySize, 61440);
    cudaFuncSetAttribute(ctx_mma,   cudaFuncAttributeMaxDynamicSharedMemorySize, 61440);
    cudaFuncSetAttribute(proj_mma,  cudaFuncAttributeMaxDynamicSharedMemorySize, 61440);
    cudaFuncSetAttribute(proj_h16,  cudaFuncAttributeMaxDynamicSharedMemorySize, 61440);
    cudaFuncSetAttribute(gate_mma,  cudaFuncAttributeMaxDynamicSharedMemorySize, 61440);

    const dim3 tpb(256);
    const dim3 proj_grid(M_TOT / 128, 4);

    // Input acats + weight cats
    convert_split<<<16384, tpb>>>(q_in_r, q_in_i, p_acat1);
    convert_split<<<16384, tpb>>>(kv_in_r, kv_in_i, p_acat2);
    convert_wcat<<<512, tpb>>>(q_wr, q_wi, p_wq);
    convert_wcat<<<512, tpb>>>(k_wr, k_wi, p_wk);
    convert_wcat<<<512, tpb>>>(v_wr, v_wi, p_wv);
    convert_wcat<<<512, tpb>>>(o_wr, o_wi, p_wo);
    convert_wgate<<<128, tpb>>>(gate_w, p_wg);

    // q/k/v projections -> fp16 cats directly
    proj_h16<<<proj_grid, tpb, 61440>>>(p_acat1, p_wq, q_br, q_bi, p_qcat);
    proj_h16<<<proj_grid, tpb, 61440>>>(p_acat2, p_wk, k_br, k_bi, p_kcat);
    proj_h16<<<proj_grid, tpb, 61440>>>(p_acat2, p_wv, v_br, v_bi, p_vcat);
    transpose_v<<<dim3(T_SEQ/32, D_MOD/32, N_BH), dim3(32, 8)>>>(p_vcat, p_vtr, p_vti);

    // Attention
    score_mma<<<dim3(16, 16, N_BH), tpb, 61440>>>(p_qcat, p_kcat, p_sc);
    softmax_rows<<<(unsigned)(N_BH * T_SEQ), tpb>>>(p_sc, p_attn);
    // ctx writes o-proj input acat directly (acat2 free after k/v projections)
    ctx_mma<<<dim3(16, 2, 2 * N_BH), tpb, 61440>>>(p_attn, p_vtr, p_vti, p_acat2);

    // Output projection (fp32 out) + fused gate/finalize
    proj_mma<<<proj_grid, tpb, 61440>>>(p_acat2, p_wo, o_br, o_bi, p_or, p_oi);
    convert_mag<<<16384, tpb>>>(p_or, p_oi, p_qcat);   // reuse qcat as magcat
    gate_mma<<<dim3(M_TOT / 128, 2), tpb, 61440>>>(p_qcat, p_wg, gate_b,
                                                   p_or, p_oi, (float*)d_out);
}

// round 17
// speedup vs baseline: 1.2934x; 1.0087x over previous
#include <cuda_runtime.h>
#include <cuda_bf16.h>
#include <cuda_fp16.h>
#include <math.h>
#include <stdint.h>

#define T_SEQ 2048
#define D_MOD 256
#define N_BH  32
#define M_TOT (N_BH * T_SEQ)   /* 65536 */
#define EPS_F 1e-8f
#define KCAT  1024              /* split-fp16 K for projections */
#define KSC   512               /* fp16 K for scores / gate */

// ---- scratch (device globals; no runtime allocation allowed) ----
__device__ float g_outr[M_TOT * D_MOD];
__device__ float g_outi[M_TOT * D_MOD];
__device__ float g_sc[(size_t)N_BH * T_SEQ * T_SEQ];          /* 512 MB fp32 scores */
__device__ __half g_attn[(size_t)N_BH * T_SEQ * T_SEQ];       /* 256 MB fp16 attn  */
__device__ __half g_qcat[(size_t)M_TOT * KSC];                /* 64 MB  [hr|hi] / magcat */
__device__ __half g_kcat[(size_t)M_TOT * KSC];                /* 64 MB  [hr|hi]    */
__device__ __half g_vcat[(size_t)M_TOT * KSC];                /* 64 MB  [hr|hi]    */
__device__ __half g_acat1[(size_t)M_TOT * KCAT];              /* 128 MB q input acat */
__device__ __half g_acat2[(size_t)M_TOT * KCAT];              /* 128 MB kv acat / ctx acat */
__device__ __half g_vtr[(size_t)N_BH * D_MOD * T_SEQ];        /* 32 MB V^T fp16    */
__device__ __half g_vti[(size_t)N_BH * D_MOD * T_SEQ];        /* 32 MB V^T fp16    */
__device__ __half g_wq[512 * KCAT];                           /* 1 MB weight cat   */
__device__ __half g_wk[512 * KCAT];
__device__ __half g_wv[512 * KCAT];
__device__ __half g_wo[512 * KCAT];
__device__ __half g_wg[256 * KSC];                            /* gate W cat        */

// ============================================================================
// helpers
// ============================================================================
__device__ __forceinline__ uint32_t smem_to_u32(const void* smem_ptr) {
    uint32_t addr;
    asm("{ .reg .u64 tmp; cvta.to.shared.u64 tmp, %1; cvt.u32.u64 %0, tmp; }"
        : "=r"(addr) : "l"(smem_ptr));
    return addr;
}
__device__ __forceinline__ void cp16(uint32_t smem_addr, const void* gptr) {
    asm volatile("cp.async.cg.shared.global [%0], [%1], 16;"
                 :: "r"(smem_addr), "l"(gptr) : "memory");
}
__device__ __forceinline__ void ldsm_x4(uint32_t* r, uint32_t addr) {
    asm volatile("ldmatrix.sync.aligned.m8n8.x4.shared.b16 {%0,%1,%2,%3}, [%4];"
                 : "=r"(r[0]), "=r"(r[1]), "=r"(r[2]), "=r"(r[3]) : "r"(addr));
}
__device__ __forceinline__ void ldsm_x2(uint32_t* r, uint32_t addr) {
    asm volatile("ldmatrix.sync.aligned.m8n8.x2.shared.b16 {%0,%1}, [%2];"
                 : "=r"(r[0]), "=r"(r[1]) : "r"(addr));
}
__device__ __forceinline__ void mma_f16(float* d, const uint32_t* a, const uint32_t* b) {
    asm volatile(
        "mma.sync.aligned.m16n8k16.row.col.f32.f16.f16.f32 "
        "{%0,%1,%2,%3}, {%4,%5,%6,%7}, {%8,%9}, {%0,%1,%2,%3};"
        : "+f"(d[0]), "+f"(d[1]), "+f"(d[2]), "+f"(d[3])
        : "r"(a[0]), "r"(a[1]), "r"(a[2]), "r"(a[3]), "r"(b[0]), "r"(b[1]));
}
__device__ __forceinline__ uint32_t pack_h2(float a, float b) {
    __half2 t = __floats2half2_rn(a, b);
    return *(uint32_t*)&t;
}

// ============================================================================
// Core 128x128 NT tile GEMM on mma.sync fp16 (A,B K-major), fp32 accum.
// 256 threads = 8 warps in 2(m) x 4(n); warp tile 64x32; Kblk=32.
// 4-stage cp.async pipeline, ONE __syncthreads per iteration.
// Safety: order is wait_group -> sync -> issue(it+3) -> compute(it).
//   At the sync, all threads finished iter it-1 reads, so writing stage
//   (it+3)%4 == (it-1)%4 is hazard-free; stage it%4 is not rewritten until
//   iter it+1's post-sync issue (by which time all compute(it) is done).
// Epilogue callback: epi(row, col, v0, v1).
// ============================================================================
#define SBUF_B   10240u
#define STAGE_B  20480u

template<int KTOT, typename Epi>
__device__ __forceinline__ void gemm_mma_core(
    const uint16_t* __restrict__ Ag, const uint16_t* __restrict__ Bg, Epi epi)
{
    extern __shared__ uint16_t sh16[];
    const uint32_t base = smem_to_u32(sh16);
    const int tid = threadIdx.x;
    const int wid = tid >> 5, lane = tid & 31;
    const int wm = wid & 1, wn = wid >> 1;

    float acc[4][4][4];
#pragma unroll
    for (int i = 0; i < 4; i++)
#pragma unroll
        for (int j = 0; j < 4; j++)
#pragma unroll
            for (int v = 0; v < 4; v++) acc[i][j][v] = 0.f;

    const int c0 = tid, c1 = tid + 256;
    const int r0 = c0 >> 2, o0 = (c0 & 3) * 8;
    const int r1 = c1 >> 2, o1 = (c1 & 3) * 8;
    const uint32_t s0 = (uint32_t)((r0 * 40 + o0) * 2);
    const uint32_t s1 = (uint32_t)((r1 * 40 + o1) * 2);

    constexpr int NIT = KTOT / 32;

#define ISSUE_STAGE(stg, itk) do {                                          \
        const uint32_t sb_ = base + (uint32_t)(stg) * STAGE_B;              \
        const int k0_ = (itk) * 32;                                         \
        cp16(sb_ + s0,          Ag + (size_t)r0 * KTOT + k0_ + o0);         \
        cp16(sb_ + SBUF_B + s0, Bg + (size_t)r0 * KTOT + k0_ + o0);         \
        cp16(sb_ + s1,          Ag + (size_t)r1 * KTOT + k0_ + o1);         \
        cp16(sb_ + SBUF_B + s1, Bg + (size_t)r1 * KTOT + k0_ + o1);         \
        asm volatile("cp.async.commit_group;" ::: "memory");                \
    } while (0)

    ISSUE_STAGE(0, 0);
    if (NIT > 1) ISSUE_STAGE(1, 1);
    if (NIT > 2) ISSUE_STAGE(2, 2);

    for (int it = 0; it < NIT; it++) {
        // groups issued so far have ids 0..it+2; need id `it` complete.
        if (it + 2 < NIT) {
            asm volatile("cp.async.wait_group 2;" ::: "memory");
        } else if (it + 1 < NIT) {
            asm volatile("cp.async.wait_group 1;" ::: "memory");
        } else {
            asm volatile("cp.async.wait_group 0;" ::: "memory");
        }
        __syncthreads();
        if (it + 3 < NIT) ISSUE_STAGE((it + 3) & 3, it + 3);

        const uint32_t ab = base + (uint32_t)(it & 3) * STAGE_B;
        const uint32_t bb = ab + SBUF_B;
#pragma unroll
        for (int ks = 0; ks < 32; ks += 16) {
            uint32_t af[4][4], bf[4][2];
            const int ar = lane & 15, ac = ks + ((lane >> 4) << 3);
#pragma unroll
            for (int i = 0; i < 4; i++)
                ldsm_x4(af[i], ab + (uint32_t)(((wm * 64 + i * 16 + ar) * 40 + ac) << 1));
            const int l = lane & 15;
            const int br_ = l & 7, bc = ks + ((l >> 3) << 3);
#pragma unroll
            for (int j = 0; j < 4; j++)
                ldsm_x2(bf[j], bb + (uint32_t)(((wn * 32 + j * 8 + br_) * 40 + bc) << 1));
#pragma unroll
            for (int i = 0; i < 4; i++)
#pragma unroll
                for (int j = 0; j < 4; j++)
                    mma_f16(acc[i][j], af[i], bf[j]);
        }
    }
#undef ISSUE_STAGE
    __syncthreads();

#pragma unroll
    for (int i = 0; i < 4; i++) {
        const int row = wm * 64 + i * 16 + (lane >> 2);
#pragma unroll
        for (int j = 0; j < 4; j++) {
            const int col = wn * 32 + j * 8 + (lane & 3) * 2;
            epi(row,     col, acc[i][j][0], acc[i][j][1]);
            epi(row + 8, col, acc[i][j][2], acc[i][j][3]);
        }
    }
}

#define GEMM_SMEM 81920

// ============================================================================
// Scores: S = Qcat @ Kcat^T * 1/16, K=512 fp16 ([hr|hi] both sides)
// ============================================================================
__global__ __launch_bounds__(256) void score_mma(
    const __half* __restrict__ Q, const __half* __restrict__ K,
    float* __restrict__ S)
{
    const int head = blockIdx.z;
    const int bm = blockIdx.x * 128, bn = blockIdx.y * 128;
    const uint16_t* A = (const uint16_t*)(Q + ((size_t)head * T_SEQ + bm) * KSC);
    const uint16_t* B = (const uint16_t*)(K + ((size_t)head * T_SEQ + bn) * KSC);
    float* C = S + ((size_t)head * T_SEQ + bm) * T_SEQ + bn;
    auto epi = [&](int r, int c, float v0, float v1) {
        *(float2*)(C + (size_t)r * T_SEQ + c) = make_float2(v0 * 0.0625f, v1 * 0.0625f);
    };
    gemm_mma_core<KSC>(A, B, epi);
}

// ============================================================================
// Context: attn @ Vt^T, fp16, K=2048. grid (16, 2, 64) z=head*2+part.
// Epilogue writes h/l split DIRECTLY into acat [M,1024]:
//   part=0 (real): h at +c, l at +256+c ; part=1 (imag): h at +512+c, l at +768+c
// ============================================================================
__global__ __launch_bounds__(256) void ctx_mma(
    const __half* __restrict__ Attn, const __half* __restrict__ Vtr,
    const __half* __restrict__ Vti, __half* __restrict__ Acat)
{
    const int bz = blockIdx.z;
    const int head = bz >> 1, part = bz & 1;
    const int bm = blockIdx.x * 128, bn = blockIdx.y * 128;
    const uint16_t* A = (const uint16_t*)(Attn + ((size_t)head * T_SEQ + bm) * T_SEQ);
    const __half* Vt = part ? Vti : Vtr;
    const uint16_t* B = (const uint16_t*)(Vt + ((size_t)head * D_MOD + bn) * T_SEQ);
    const size_t rbase = (size_t)head * T_SEQ + bm;
    const int hoff = part * 512;
    auto epi = [&](int r, int c, float v0, float v1) {
        uint32_t* out = (uint32_t*)(Acat + (rbase + r) * KCAT);
        float h0f = __half2float(__float2half_rn(v0));
        float h1f = __half2float(__float2half_rn(v1));
        const int gc = bn + c;
        out[(hoff + gc) >> 1]       = pack_h2(h0f, h1f);
        out[(hoff + 256 + gc) >> 1] = pack_h2(v0 - h0f, v1 - h1f);
    };
    gemm_mma_core<T_SEQ>(A, B, epi);
}

// ============================================================================
// Projection (fp16-cat output, for q/k/v):
// A_cat [M,1024] = [h(Ar)|l(Ar)|h(Ai)|l(Ai)], W_cat [512,1024] (see convert_wcat).
// Epilogue: +bias, convert to fp16, write cat[row*512 + (i?256:0) + col].
// grid (M/128, 4).
// ============================================================================
__global__ __launch_bounds__(256) void proj_h16(
    const __half* __restrict__ Acat, const __half* __restrict__ Wcat,
    const float* __restrict__ bR, const float* __restrict__ bI,
    __half* __restrict__ Cat)
{
    const int bm = blockIdx.x * 128, bn = blockIdx.y * 128;
    const uint16_t* A = (const uint16_t*)(Acat + (size_t)bm * KCAT);
    const uint16_t* B = (const uint16_t*)(Wcat + (size_t)bn * KCAT);
    const float* bias = (bn >= 256) ? bI : bR;
    const int off = (bn >= 256) ? 256 + (bn & 255) : bn;
    auto epi = [&](int r, int c, float v0, float v1) {
        const int gc = (bn & 255) + c;
        *(uint32_t*)(Cat + (size_t)(bm + r) * KSC + off + c)
            = pack_h2(v0 + __ldg(bias + gc), v1 + __ldg(bias + gc + 1));
    };
    gemm_mma_core<KCAT>(A, B, epi);
}

// ============================================================================
// Projection (fp32 output, for o): +bias, write Cr/Ci. grid (M/128, 4).
// ============================================================================
__global__ __launch_bounds__(256) void proj_mma(
    const __half* __restrict__ Acat, const __half* __restrict__ Wcat,
    const float* __restrict__ bR, const float* __restrict__ bI,
    float* __restrict__ Cr, float* __restrict__ Ci)
{
    const int bm = blockIdx.x * 128, bn = blockIdx.y * 128;
    const uint16_t* A = (const uint16_t*)(Acat + (size_t)bm * KCAT);
    const uint16_t* B = (const uint16_t*)(Wcat + (size_t)bn * KCAT);
    float* Cbase = (bn >= 256) ? Ci : Cr;
    const float* bias = (bn >= 256) ? bI : bR;
    const int coff = bn & 255;
    auto epi = [&](int r, int c, float v0, float v1) {
        const int gc = coff + c;
        *(float2*)(Cbase + (size_t)(bm + r) * D_MOD + gc)
            = make_float2(v0 + __ldg(bias + gc), v1 + __ldg(bias + gc + 1));
    };
    gemm_mma_core<KCAT>(A, B, epi);
}

// ============================================================================
// Gate + finalize fused: G = sigmoid(magcat @ Wg^T + b); out = (Or*G, Oi*G)
// magcat [M,512] = [h(mag)|l(mag)], Wg [256,512]. grid (M/128, 2).
// ============================================================================
__global__ __launch_bounds__(256) void gate_mma(
    const __half* __restrict__ Mag, const __half* __restrict__ Wg,
    const float* __restrict__ bias,
    const float* __restrict__ Or, const float* __restrict__ Oi,
    float* __restrict__ out)
{
    const int bm = blockIdx.x * 128, bn = blockIdx.y * 128;
    const uint16_t* A = (const uint16_t*)(Mag + (size_t)bm * KSC);
    const uint16_t* B = (const uint16_t*)(Wg + (size_t)bn * KSC);
    auto epi = [&](int r, int c, float v0, float v1) {
        const int gc = bn + c;
        const size_t row = (size_t)(bm + r);
        float g0 = 1.f / (1.f + __expf(-(v0 + __ldg(bias + gc))));
        float g1 = 1.f / (1.f + __expf(-(v1 + __ldg(bias + gc + 1))));
        float2 a = *(const float2*)(Or + row * D_MOD + gc);
        float2 b = *(const float2*)(Oi + row * D_MOD + gc);
        *(float2*)(out + row * D_MOD + gc) = make_float2(a.x * g0, a.y * g1);
        *(float2*)(out + (size_t)M_TOT * D_MOD + row * D_MOD + gc)
            = make_float2(b.x * g0, b.y * g1);
    };
    gemm_mma_core<KSC>(A, B, epi);
}

// ============================================================================
// Build W_cat [512,1024] fp16 from Wr, Wi [256,256] fp32. grid 512 x 256 thr.
//   rows 0-255  (Cr): [h(Wr)|h(Wr)|h(-Wi)|h(-Wi)]
//   rows 256-511(Ci): [h(Wi)|h(Wi)|h(Wr) |h(Wr) ]
// ============================================================================
__global__ __launch_bounds__(256) void convert_wcat(
    const float* __restrict__ Wr, const float* __restrict__ Wi,
    __half* __restrict__ Wcat)
{
    const int t = blockIdx.x * 256 + threadIdx.x;
    const int r = t >> 8;
    const int c = (t & 255) * 4;
    const int seg = c >> 8;
    const int k = c & 255;
    const int m = r & 255;
    const float* src;
    float sign = 1.f;
    if (r < 256) { if (seg < 2) src = Wr; else { src = Wi; sign = -1.f; } }
    else         { src = (seg < 2) ? Wi : Wr; }
    float4 w = *(const float4*)(src + (size_t)m * 256 + k);
    uint32_t* out = (uint32_t*)(Wcat + (size_t)r * KCAT + c);
    out[0] = pack_h2(sign * w.x, sign * w.y);
    out[1] = pack_h2(sign * w.z, sign * w.w);
}

// Gate weight cat [256,512] = [h(W)|h(W)]. 128 blocks x 256 thr.
__global__ __launch_bounds__(256) void convert_wgate(
    const float* __restrict__ W, __half* __restrict__ Wg)
{
    const int t = blockIdx.x * 256 + threadIdx.x;
    const int r = t >> 7;
    const int c = (t & 127) * 4;
    const int k = c & 255;
    float4 w = *(const float4*)(W + (size_t)r * 256 + k);
    uint32_t* out = (uint32_t*)(Wg + (size_t)r * KSC + c);
    out[0] = pack_h2(w.x, w.y);
    out[1] = pack_h2(w.z, w.w);
}

// ============================================================================
// Input split-fp16 conversion -> row of 1024 fp16 [h(r)|l(r)|h(i)|l(i)].
// ============================================================================
__global__ __launch_bounds__(256) void convert_split(
    const float* __restrict__ Xr, const float* __restrict__ Xi,
    __half* __restrict__ cat)
{
    const size_t t = (size_t)blockIdx.x * 256 + threadIdx.x;
    const size_t row = t >> 6;
    const int c = (int)(t & 63) << 2;
    float4 xr = *(const float4*)(Xr + row*256 + c);
    float4 xi = *(const float4*)(Xi + row*256 + c);
    float vr[4] = {xr.x, xr.y, xr.z, xr.w};
    float vi[4] = {xi.x, xi.y, xi.z, xi.w};
    float hr[4], lr[4], hi[4], li[4];
#pragma unroll
    for (int j = 0; j < 4; j++) {
        __half h = __float2half_rn(vr[j]);
        hr[j] = __half2float(h); lr[j] = vr[j] - hr[j];
        __half g = __float2half_rn(vi[j]);
        hi[j] = __half2float(g); li[j] = vi[j] - hi[j];
    }
    uint32_t* out = (uint32_t*)(cat + row * KCAT);
    const int c2 = c >> 1;
    out[c2]         = pack_h2(hr[0], hr[1]); out[c2+1]       = pack_h2(hr[2], hr[3]);
    out[128 + c2]   = pack_h2(lr[0], lr[1]); out[128 + c2+1] = pack_h2(lr[2], lr[3]);
    out[256 + c2]   = pack_h2(hi[0], hi[1]); out[256 + c2+1] = pack_h2(hi[2], hi[3]);
    out[384 + c2]   = pack_h2(li[0], li[1]); out[384 + c2+1] = pack_h2(li[2], li[3]);
}

// ============================================================================
// Mag split: outr/outi fp32 -> magcat [M,512] = [h(mag)|l(mag)]
// ============================================================================
__global__ __launch_bounds__(256) void convert_mag(
    const float* __restrict__ Or, const float* __restrict__ Oi,
    __half* __restrict__ Mag)
{
    const size_t t = (size_t)blockIdx.x * 256 + threadIdx.x;
    const size_t row = t >> 6;
    const int c = (int)(t & 63) << 2;
    float4 a = *(const float4*)(Or + row*256 + c);
    float4 b = *(const float4*)(Oi + row*256 + c);
    float m[4] = {sqrtf(a.x*a.x + b.x*b.x + EPS_F), sqrtf(a.y*a.y + b.y*b.y + EPS_F),
                  sqrtf(a.z*a.z + b.z*b.z + EPS_F), sqrtf(a.w*a.w + b.w*b.w + EPS_F)};
    float h[4], l[4];
#pragma unroll
    for (int j = 0; j < 4; j++) {
        __half hh = __float2half_rn(m[j]);
        h[j] = __half2float(hh); l[j] = m[j] - h[j];
    }
    uint32_t* out = (uint32_t*)(Mag + row * KSC);
    const int c2 = c >> 1;
    out[c2]         = pack_h2(h[0], h[1]); out[c2+1]       = pack_h2(h[2], h[3]);
    out[128 + c2]   = pack_h2(l[0], l[1]); out[128 + c2+1] = pack_h2(l[2], l[3]);
}

// ============================================================================
// Transpose V: vcat fp16 [bh*T_SEQ][512]([hr|hi]) -> Vt[bh][n=256][k=2048] fp16
// ============================================================================
__global__ void transpose_v(
    const __half* __restrict__ Vcat,
    __half* __restrict__ Vtr, __half* __restrict__ Vti)
{
    __shared__ __half tr[32][33], ti[32][33];
    const int head = blockIdx.z;
    const int k0 = blockIdx.x * 32, n0 = blockIdx.y * 32;
    const int tx = threadIdx.x, ty = threadIdx.y;
    const size_t ibase = (size_t)head * T_SEQ;
#pragma unroll
    for (int i = 0; i < 32; i += 8) {
        const __half* src = Vcat + (ibase + k0 + ty + i) * KSC;
        tr[ty+i][tx] = src[n0 + tx];
        ti[ty+i][tx] = src[256 + n0 + tx];
    }
    __syncthreads();
    const size_t obase = ((size_t)head * 256 + n0) * T_SEQ + k0;
#pragma unroll
    for (int i = 0; i < 32; i += 8) {
        Vtr[obase + (size_t)(ty+i)*T_SEQ + tx] = tr[tx][ty+i];
        Vti[obase + (size_t)(ty+i)*T_SEQ + tx] = ti[tx][ty+i];
    }
}

// ============================================================================
// Row softmax: read fp32 scores, write fp16 attn
// ============================================================================
__global__ __launch_bounds__(256) void softmax_rows(
    const float* __restrict__ S, __half* __restrict__ A)
{
    const float* p = S + (size_t)blockIdx.x * T_SEQ;
    __half* ap = A + (size_t)blockIdx.x * T_SEQ;
    const int tid = threadIdx.x;
    float v[8];
    float m = -3.4e38f;
#pragma unroll
    for (int r = 0; r < 8; r++) { v[r] = p[tid + (r << 8)]; m = fmaxf(m, v[r]); }
#pragma unroll
    for (int o = 16; o > 0; o >>= 1) m = fmaxf(m, __shfl_xor_sync(0xffffffffu, m, o));
    __shared__ float red[8];
    if ((tid & 31) == 0) red[tid >> 5] = m;
    __syncthreads();
    m = red[0];
#pragma unroll
    for (int w = 1; w < 8; w++) m = fmaxf(m, red[w]);
    float sum = 0.f;
#pragma unroll
    for (int r = 0; r < 8; r++) { v[r] = __expf(v[r] - m); sum += v[r]; }
#pragma unroll
    for (int o = 16; o > 0; o >>= 1) sum += __shfl_xor_sync(0xffffffffu, sum, o);
    __syncthreads();
    if ((tid & 31) == 0) red[tid >> 5] = sum;
    __syncthreads();
    sum = 0.f;
#pragma unroll
    for (int w = 0; w < 8; w++) sum += red[w];
    const float inv = 1.f / sum;
#pragma unroll
    for (int r = 0; r < 8; r++) ap[tid + (r << 8)] = __float2half(v[r] * inv);
}

// ============================================================================
extern "C" void kernel_launch(void* const* d_in, const int* in_sizes, int n_in,
                              void* d_out, int out_size)
{
    const float* q_in_r  = (const float*)d_in[0];
    const float* q_in_i  = (const float*)d_in[1];
    const float* kv_in_r = (const float*)d_in[2];
    const float* kv_in_i = (const float*)d_in[3];
    const float* q_wr = (const float*)d_in[4];
    const float* q_wi = (const float*)d_in[5];
    const float* q_br = (const float*)d_in[6];
    const float* q_bi = (const float*)d_in[7];
    const float* k_wr = (const float*)d_in[8];
    const float* k_wi = (const float*)d_in[9];
    const float* k_br = (const float*)d_in[10];
    const float* k_bi = (const float*)d_in[11];
    const float* v_wr = (const float*)d_in[12];
    const float* v_wi = (const float*)d_in[13];
    const float* v_br = (const float*)d_in[14];
    const float* v_bi = (const float*)d_in[15];
    const float* o_wr = (const float*)d_in[16];
    const float* o_wi = (const float*)d_in[17];
    const float* o_br = (const float*)d_in[18];
    const float* o_bi = (const float*)d_in[19];
    const float* gate_w = (const float*)d_in[20];
    const float* gate_b = (const float*)d_in[21];

    float *p_or, *p_oi, *p_sc;
    __half *p_attn, *p_vtr, *p_vti, *p_qcat, *p_kcat, *p_vcat, *p_acat1, *p_acat2;
    __half *p_wq, *p_wk, *p_wv, *p_wo, *p_wg;
    cudaGetSymbolAddress((void**)&p_or, g_outr);
    cudaGetSymbolAddress((void**)&p_oi, g_outi);
    cudaGetSymbolAddress((void**)&p_sc, g_sc);
    cudaGetSymbolAddress((void**)&p_attn, g_attn);
    cudaGetSymbolAddress((void**)&p_qcat, g_qcat);
    cudaGetSymbolAddress((void**)&p_kcat, g_kcat);
    cudaGetSymbolAddress((void**)&p_vcat, g_vcat);
    cudaGetSymbolAddress((void**)&p_acat1, g_acat1);
    cudaGetSymbolAddress((void**)&p_acat2, g_acat2);
    cudaGetSymbolAddress((void**)&p_vtr, g_vtr);
    cudaGetSymbolAddress((void**)&p_vti, g_vti);
    cudaGetSymbolAddress((void**)&p_wq, g_wq);
    cudaGetSymbolAddress((void**)&p_wk, g_wk);
    cudaGetSymbolAddress((void**)&p_wv, g_wv);
    cudaGetSymbolAddress((void**)&p_wo, g_wo);
    cudaGetSymbolAddress((void**)&p_wg, g_wg);

    cudaFuncSetAttribute(score_mma, cudaFuncAttributeMaxDynamicSharedMemorySize, GEMM_SMEM);
    cudaFuncSetAttribute(ctx_mma,   cudaFuncAttributeMaxDynamicSharedMemorySize, GEMM_SMEM);
    cudaFuncSetAttribute(proj_mma,  cudaFuncAttributeMaxDynamicSharedMemorySize, GEMM_SMEM);
    cudaFuncSetAttribute(proj_h16,  cudaFuncAttributeMaxDynamicSharedMemorySize, GEMM_SMEM);
    cudaFuncSetAttribute(gate_mma,  cudaFuncAttributeMaxDynamicSharedMemorySize, GEMM_SMEM);

    const dim3 tpb(256);
    const dim3 proj_grid(M_TOT / 128, 4);

    // Input acats + weight cats
    convert_split<<<16384, tpb>>>(q_in_r, q_in_i, p_acat1);
    convert_split<<<16384, tpb>>>(kv_in_r, kv_in_i, p_acat2);
    convert_wcat<<<512, tpb>>>(q_wr, q_wi, p_wq);
    convert_wcat<<<512, tpb>>>(k_wr, k_wi, p_wk);
    convert_wcat<<<512, tpb>>>(v_wr, v_wi, p_wv);
    convert_wcat<<<512, tpb>>>(o_wr, o_wi, p_wo);
    convert_wgate<<<128, tpb>>>(gate_w, p_wg);

    // q/k/v projections -> fp16 cats directly
    proj_h16<<<proj_grid, tpb, GEMM_SMEM>>>(p_acat1, p_wq, q_br, q_bi, p_qcat);
    proj_h16<<<proj_grid, tpb, GEMM_SMEM>>>(p_acat2, p_wk, k_br, k_bi, p_kcat);
    proj_h16<<<proj_grid, tpb, GEMM_SMEM>>>(p_acat2, p_wv, v_br, v_bi, p_vcat);
    transpose_v<<<dim3(T_SEQ/32, D_MOD/32, N_BH), dim3(32, 8)>>>(p_vcat, p_vtr, p_vti);

    // Attention
    score_mma<<<dim3(16, 16, N_BH), tpb, GEMM_SMEM>>>(p_qcat, p_kcat, p_sc);
    softmax_rows<<<(unsigned)(N_BH * T_SEQ), tpb>>>(p_sc, p_attn);
    // ctx writes o-proj input acat directly (acat2 free after k/v projections)
    ctx_mma<<<dim3(16, 2, 2 * N_BH), tpb, GEMM_SMEM>>>(p_attn, p_vtr, p_vti, p_acat2);

    // Output projection (fp32 out) + fused gate/finalize
    proj_mma<<<proj_grid, tpb, GEMM_SMEM>>>(p_acat2, p_wo, o_br, o_bi, p_or, p_oi);
    convert_mag<<<16384, tpb>>>(p_or, p_oi, p_qcat);   // reuse qcat as magcat
    gate_mma<<<dim3(M_TOT / 128, 2), tpb, GEMM_SMEM>>>(p_qcat, p_wg, gate_b,
                                                       p_or, p_oi, (float*)d_out);
}